// round 15
// baseline (speedup 1.0000x reference)
#include <cuda_runtime.h>
#include <cuda_fp16.h>
#include <stdint.h>
#include <math_constants.h>

#define K_CODES 8192
#define DIM     256
#define NTOK    32768
#define HW      1024

#define OUT_LOSS 0
#define OUT_Q    1
#define OUT_IDX  (OUT_Q  + 32*DIM*HW)
#define OUT_CNT  (OUT_IDX + NTOK)
#define OUT_W    (OUT_CNT + K_CODES)
#define OUT_CB   (OUT_W   + K_CODES*DIM)

#define WINDOW 3.0e-4f
#define NTILE  (K_CODES / 128)   // 64
#define CAP    12

// ---------------- device scratch ----------------
__device__ __align__(128) __half g_x16T[NTOK * DIM];     // half(x), [token][d]
__device__ __align__(128) __half g_cb16[K_CODES * DIM];  // half(cb * 2^13), [code][d]
__device__ float  g_cbnorm[K_CODES];
__device__ float  g_znorm[NTOK];
__device__ double g_zpart[8][NTOK];
__device__ float  g_counts[K_CODES];
__device__ float  g_dw[K_CODES * DIM];
__device__ double g_loss;
__device__ int    g_idx[NTOK];
__device__ int    g_ovf_cnt;
__device__ int    g_ovf[NTOK];

__device__ __forceinline__ uint32_t smem_u32(const void* p) {
    uint32_t a;
    asm("{ .reg .u64 t; cvta.to.shared.u64 t, %1; cvt.u32.u64 %0, t; }" : "=r"(a) : "l"(p));
    return a;
}
__device__ __forceinline__ unsigned int enc_f(float d) {
    unsigned int e = __float_as_uint(d);
    return (e & 0x80000000u) ? ~e : (e | 0x80000000u);
}
__device__ __forceinline__ float dec_f(unsigned int v) {
    unsigned int b = (v & 0x80000000u) ? (v & 0x7FFFFFFFu) : ~v;
    return __uint_as_float(b);
}
#define CP16(dst, src) \
    asm volatile("cp.async.ca.shared.global [%0], [%1], 16;" :: "r"(dst), "l"(src))
#define CP_COMMIT() asm volatile("cp.async.commit_group;" ::: "memory")
#define CP_WAIT0()  asm volatile("cp.async.wait_group 0;" ::: "memory")

#define MMA_F16(c, a, b) \
    asm volatile("mma.sync.aligned.m16n8k16.row.col.f32.f16.f16.f32 " \
        "{%0,%1,%2,%3}, {%4,%5,%6,%7}, {%8,%9}, {%0,%1,%2,%3};" \
        : "+f"((c)[0]), "+f"((c)[1]), "+f"((c)[2]), "+f"((c)[3]) \
        : "r"((a)[0]), "r"((a)[1]), "r"((a)[2]), "r"((a)[3]), "r"((b)[0]), "r"((b)[1]))

// ---------------- init ----------------
__global__ void init_kernel() {
    int i = blockIdx.x * blockDim.x + threadIdx.x;
    if (i < K_CODES * DIM) g_dw[i] = 0.0f;
    if (i < K_CODES)       g_counts[i] = 0.0f;
    if (i == 0)            { g_loss = 0.0; g_ovf_cnt = 0; }
}

// ---------------- x -> half [token][d]  +  znorm partials (fused) ----------------
// block (32,32): tile of 32 hw x 32 d for one b. After transpose each warp (ty)
// holds one token's 32 d-values across lanes -> fp64 shuffle-reduce partial.
__global__ void decomp_x16T(const float* __restrict__ x) {
    __shared__ float tile[32][33];
    int tx = threadIdx.x, ty = threadIdx.y;
    int hw0 = blockIdx.x * 32, d0 = blockIdx.y * 32, b = blockIdx.z;
    tile[ty][tx] = x[(size_t)b * DIM * HW + (size_t)(d0 + ty) * HW + hw0 + tx];
    __syncthreads();
    float v = tile[tx][ty];                       // token = b*1024+hw0+ty, d = d0+tx
    int token = b * 1024 + hw0 + ty;
    g_x16T[(size_t)token * DIM + d0 + tx] = __float2half_rn(v);
    double s = (double)v * (double)v;
    #pragma unroll
    for (int o = 16; o; o >>= 1) s += __shfl_down_sync(0xFFFFFFFFu, s, o);
    if (tx == 0) g_zpart[d0 >> 5][token] = s;
}
__global__ void znorm_comb() {
    int token = blockIdx.x * blockDim.x + threadIdx.x;
    double a0 = (g_zpart[0][token] + g_zpart[1][token])
              + (g_zpart[2][token] + g_zpart[3][token]);
    double a1 = (g_zpart[4][token] + g_zpart[5][token])
              + (g_zpart[6][token] + g_zpart[7][token]);
    g_znorm[token] = (float)(a0 + a1);
}

// ---------------- cb -> half(cb*2^13) + cbnorm (fused; warp per code) ----------
__global__ void decomp_cb16(const float* __restrict__ cb) {
    int gw = (blockIdx.x * blockDim.x + threadIdx.x) >> 5;  // code
    int lane = threadIdx.x & 31;
    const float* r = cb + (size_t)gw * DIM + lane * 8;
    float4 v0 = *(const float4*)r;
    float4 v1 = *(const float4*)(r + 4);
    __half2 h[4];
    h[0] = __floats2half2_rn(v0.x * 8192.0f, v0.y * 8192.0f);
    h[1] = __floats2half2_rn(v0.z * 8192.0f, v0.w * 8192.0f);
    h[2] = __floats2half2_rn(v1.x * 8192.0f, v1.y * 8192.0f);
    h[3] = __floats2half2_rn(v1.z * 8192.0f, v1.w * 8192.0f);
    *(uint4*)(g_cb16 + (size_t)gw * DIM + lane * 8) = *(uint4*)h;
    double s = 0.0;
    const float vv[8] = {v0.x, v0.y, v0.z, v0.w, v1.x, v1.y, v1.z, v1.w};
    #pragma unroll
    for (int i = 0; i < 8; i++) s = fma((double)vv[i], (double)vv[i], s);
    #pragma unroll
    for (int o = 16; o; o >>= 1) s += __shfl_down_sync(0xFFFFFFFFu, s, o);
    if (lane == 0) g_cbnorm[gw] = (float)s;
}

// ---------------- fused screening + argmin + rescore (token-stationary) --------
// 256 CTAs, one per 128-token tile; loops 64 code tiles x 8 k-chunks (512 stages).
#define AP      40
#define TILE_H  (128 * AP)
#define STAGE_H (2 * TILE_H)          // 20480 B
#define SMEM_B  (2 * STAGE_H * 2)     // 40960 B dynamic

__global__ void __launch_bounds__(256, 2)
screen_fused(const float* __restrict__ x, const float* __restrict__ cb,
             float* __restrict__ out) {
    extern __shared__ __half smh[];
    const uint32_t smb = smem_u32(smh);
    __shared__ unsigned int s_runmin[128];
    __shared__ int  s_ccnt[128];
    __shared__ int2 s_cand[128][CAP];

    const int tid  = threadIdx.x;
    const int lane = tid & 31;
    const int wid  = tid >> 5;
    const int g    = lane >> 2;
    const int q    = lane & 3;
    const int tb   = blockIdx.x;

    const int mbase = (wid & 3) * 32;
    const int nbase = (wid >> 2) * 64;

    if (tid < 128) { s_runmin[tid] = 0xFFFFFFFFu; s_ccnt[tid] = 0; }
    __syncthreads();

    float acc[2][8][4];
    #pragma unroll
    for (int mf = 0; mf < 2; mf++)
        #pragma unroll
        for (int nf = 0; nf < 8; nf++)
            #pragma unroll
            for (int c = 0; c < 4; c++) acc[mf][nf][c] = 0.0f;

    auto issue = [&](int sg) {
        int ct2 = sg >> 3, ks2 = sg & 7;
        const __half* ap = g_x16T + (size_t)(tb * 128) * DIM + ks2 * 32;
        const __half* bp = g_cb16 + (size_t)(ct2 * 128) * DIM + ks2 * 32;
        int s = sg & 1;
        #pragma unroll
        for (int i = 0; i < 2; i++) {
            int idx = i * 256 + tid;
            int row = idx >> 2;
            int seg = idx & 3;
            CP16(smb + 2u * (s * STAGE_H + row * AP + seg * 8),
                 ap + (size_t)row * DIM + seg * 8);
            CP16(smb + 2u * (s * STAGE_H + TILE_H + row * AP + seg * 8),
                 bp + (size_t)row * DIM + seg * 8);
        }
        CP_COMMIT();
    };

    issue(0);

    #pragma unroll 1
    for (int sg = 0; sg < NTILE * 8; sg++) {
        CP_WAIT0();
        __syncthreads();
        if (sg < NTILE * 8 - 1) issue(sg + 1);

        const uint32_t* A32 = (const uint32_t*)(smh + (sg & 1) * STAGE_H);
        const uint32_t* B32 = A32 + TILE_H / 2;

        #pragma unroll
        for (int kl2 = 0; kl2 < 2; kl2++) {
            const int klh = kl2 * 8;
            uint32_t af[2][4], bf[8][2];
            #pragma unroll
            for (int mf = 0; mf < 2; mf++) {
                int m = mbase + mf * 16 + g;
                af[mf][0] = A32[m * (AP / 2) + klh + q];
                af[mf][1] = A32[(m + 8) * (AP / 2) + klh + q];
                af[mf][2] = A32[m * (AP / 2) + klh + 4 + q];
                af[mf][3] = A32[(m + 8) * (AP / 2) + klh + 4 + q];
            }
            #pragma unroll
            for (int nf = 0; nf < 8; nf++) {
                int n = nbase + nf * 8 + g;
                bf[nf][0] = B32[n * (AP / 2) + klh + q];
                bf[nf][1] = B32[n * (AP / 2) + klh + 4 + q];
            }
            #pragma unroll
            for (int mf = 0; mf < 2; mf++)
                #pragma unroll
                for (int nf = 0; nf < 8; nf++)
                    MMA_F16(acc[mf][nf], af[mf], bf[nf]);
        }

        if ((sg & 7) == 7) {
            // per-tile epilogue for ct = sg>>3
            const int nt0 = (sg >> 3) * 128;
            #pragma unroll
            for (int mf = 0; mf < 2; mf++)
                #pragma unroll
                for (int h = 0; h < 2; h++) {
                    int m = mbase + mf * 16 + g + h * 8;  // token row in tile
                    float dv[16];
                    float mn = CUDART_INF_F;
                    #pragma unroll
                    for (int nf = 0; nf < 8; nf++)
                        #pragma unroll
                        for (int p = 0; p < 2; p++) {
                            int n = nbase + nf * 8 + q * 2 + p;
                            float d = fmaf(-0.000244140625f, acc[mf][nf][h * 2 + p],
                                           __ldg(&g_cbnorm[nt0 + n]));
                            dv[nf * 2 + p] = d;
                            mn = fminf(mn, d);
                        }
                    atomicMin(&s_runmin[m], enc_f(mn));
                    float thr = dec_f(s_runmin[m]) + WINDOW;
                    #pragma unroll
                    for (int nf = 0; nf < 8; nf++)
                        #pragma unroll
                        for (int p = 0; p < 2; p++)
                            if (dv[nf * 2 + p] <= thr) {
                                int pos = atomicAdd(&s_ccnt[m], 1);
                                if (pos < CAP) {
                                    int n = nbase + nf * 8 + q * 2 + p;
                                    s_cand[m][pos] =
                                        make_int2(nt0 + n, __float_as_int(dv[nf * 2 + p]));
                                }
                            }
                }
            #pragma unroll
            for (int mf = 0; mf < 2; mf++)
                #pragma unroll
                for (int nf = 0; nf < 8; nf++)
                    #pragma unroll
                    for (int c = 0; c < 4; c++) acc[mf][nf][c] = 0.0f;
        }
    }
    __syncthreads();

    // prune + exact fp64 rescore; one warp per token (strided)
    for (int tl = wid; tl < 128; tl += 8) {
        int token = tb * 128 + tl;
        int cnt = s_ccnt[tl];
        if (cnt > CAP) {
            if (lane == 0) {
                int p = atomicAdd(&g_ovf_cnt, 1);
                g_ovf[p] = token;
            }
            continue;
        }
        float thr = dec_f(s_runmin[tl]) + WINDOW;
        const int b = token >> 10, hw = token & 1023;
        const float* xbase = x + (size_t)b * DIM * HW + hw;
        const float zn = g_znorm[token];
        unsigned long long best = 0xFFFFFFFFFFFFFFFFull;
        for (int j = 0; j < cnt; j++) {
            int2 e = s_cand[tl][j];
            if (__int_as_float(e.y) > thr) continue;
            int c = e.x;
            const float* crow = cb + (size_t)c * DIM;
            double s = 0.0;
            #pragma unroll
            for (int i = 0; i < 8; i++) {
                int d = lane + i * 32;
                s = fma((double)__ldg(xbase + (size_t)d * HW),
                        (double)__ldg(crow + d), s);
            }
            #pragma unroll
            for (int o = 16; o; o >>= 1) s += __shfl_down_sync(0xFFFFFFFFu, s, o);
            if (lane == 0) {
                float dotf = (float)s;
                float t1 = __fadd_rn(zn, __ldg(&g_cbnorm[c]));
                float d  = __fsub_rn(t1, __fmul_rn(2.0f, dotf));
                unsigned long long pk =
                    ((unsigned long long)enc_f(d) << 32) | (unsigned int)c;
                if (pk < best) best = pk;
            }
        }
        if (lane == 0) {
            int id = (int)(best & 0xFFFFFFFFull);
            g_idx[token] = id;
            out[OUT_IDX + token] = (float)id;
            atomicAdd(&g_counts[id], 1.0f);
        }
    }
}

// ---------------- fallback: exact full argmin for overflow tokens --------------
__global__ void full_rescore(const float* __restrict__ x, const float* __restrict__ cb,
                             float* __restrict__ out) {
    __shared__ unsigned long long sbest;
    int n = *(volatile int*)&g_ovf_cnt;
    for (int i = blockIdx.x; i < n; i += gridDim.x) {
        int token = g_ovf[i];
        if (threadIdx.x == 0) sbest = 0xFFFFFFFFFFFFFFFFull;
        __syncthreads();
        const int b = token >> 10, hw = token & 1023;
        const float* xbase = x + (size_t)b * DIM * HW + hw;
        const float zn = g_znorm[token];
        int lane = threadIdx.x & 31, wid = threadIdx.x >> 5;
        for (int c = wid; c < K_CODES; c += 8) {
            const float* crow = cb + (size_t)c * DIM;
            double s = 0.0;
            #pragma unroll
            for (int k = 0; k < 8; k++) {
                int d = lane + k * 32;
                s = fma((double)__ldg(xbase + (size_t)d * HW),
                        (double)__ldg(crow + d), s);
            }
            #pragma unroll
            for (int o = 16; o; o >>= 1) s += __shfl_down_sync(0xFFFFFFFFu, s, o);
            if (lane == 0) {
                float dotf = (float)s;
                float t1 = __fadd_rn(zn, __ldg(&g_cbnorm[c]));
                float d  = __fsub_rn(t1, __fmul_rn(2.0f, dotf));
                atomicMin(&sbest, ((unsigned long long)enc_f(d) << 32) | (unsigned int)c);
            }
        }
        __syncthreads();
        if (threadIdx.x == 0) {
            int id = (int)(sbest & 0xFFFFFFFFull);
            g_idx[token] = id;
            out[OUT_IDX + token] = (float)id;
            atomicAdd(&g_counts[id], 1.0f);
        }
        __syncthreads();
    }
}

// ---------------- quantized output + loss + dw (fused, coalesced) ----------------
__global__ void quant_loss_dw(const float* __restrict__ x,
                              const float* __restrict__ cb,
                              float* __restrict__ out) {
    int c = blockIdx.x, b = blockIdx.y;
    int tid = threadIdx.x, lane = tid & 31;
    float ls = 0.0f;
    #pragma unroll
    for (int it = 0; it < 4; it++) {
        int hw = it * 256 + tid;
        int n  = (b << 10) + hw;
        int id = g_idx[n];
        float qv = __ldg(cb + (size_t)id * DIM + c);
        size_t off = (size_t)b * DIM * HW + (size_t)c * HW + hw;
        float xv = x[off];
        out[OUT_Q + off] = __fadd_rn(xv, __fsub_rn(qv, xv));
        float d = __fsub_rn(qv, xv);
        ls = fmaf(d, d, ls);
        atomicAdd(&g_dw[(size_t)id * DIM + c], xv);
    }
    double ds = (double)ls;
    #pragma unroll
    for (int o = 16; o; o >>= 1) ds += __shfl_down_sync(0xFFFFFFFFu, ds, o);
    if (lane == 0) atomicAdd(&g_loss, ds);
}

// ---------------- EMA finalize ----------------
__global__ void final_kernel(const float* __restrict__ ema_count,
                             const float* __restrict__ ema_weight,
                             float* __restrict__ out) {
    int k = blockIdx.x;
    int c = threadIdx.x;
    float nc = ema_count[k] * 0.95f + 0.05f * g_counts[k];
    const float denom = (float)(32768.0 + 8192.0 * 1e-5);
    nc = (nc + 1e-5f) / denom * 32768.0f;
    float w = ema_weight[(size_t)k * DIM + c] * 0.95f + 0.05f * g_dw[(size_t)k * DIM + c];
    out[OUT_W  + (size_t)k * DIM + c] = w;
    out[OUT_CB + (size_t)k * DIM + c] = w / nc;
    if (c == 0) out[OUT_CNT + k] = nc;
    if (k == 0 && c == 0) {
        double mean = g_loss / (double)((size_t)NTOK * DIM);
        out[OUT_LOSS] = 0.25f * (float)mean;
    }
}

extern "C" void kernel_launch(void* const* d_in, const int* in_sizes, int n_in,
                              void* d_out, int out_size) {
    const float* x          = (const float*)d_in[0];
    const float* cb         = (const float*)d_in[1];
    const float* ema_count  = (const float*)d_in[2];
    const float* ema_weight = (const float*)d_in[3];
    float* out = (float*)d_out;

    static int smem_set = 0;
    if (!smem_set) {
        cudaFuncSetAttribute(screen_fused,
                             cudaFuncAttributeMaxDynamicSharedMemorySize, SMEM_B);
        smem_set = 1;
    }

    init_kernel<<<(K_CODES * DIM + 255) / 256, 256>>>();
    decomp_x16T<<<dim3(HW / 32, DIM / 32, 32), dim3(32, 32)>>>(x);
    znorm_comb<<<NTOK / 256, 256>>>();
    decomp_cb16<<<K_CODES * 32 / 256, 256>>>(cb);
    screen_fused<<<NTOK / 128, 256, SMEM_B>>>(x, cb, out);
    full_rescore<<<64, 256>>>(x, cb, out);
    quant_loss_dw<<<dim3(DIM, 32), 256>>>(x, cb, out);
    final_kernel<<<K_CODES, DIM>>>(ema_count, ema_weight, out);
}

// round 16
// speedup vs baseline: 88.8097x; 88.8097x over previous
#include <cuda_runtime.h>
#include <cuda_fp16.h>
#include <stdint.h>
#include <math_constants.h>

#define K_CODES 8192
#define DIM     256
#define NTOK    32768
#define HW      1024

#define OUT_LOSS 0
#define OUT_Q    1
#define OUT_IDX  (OUT_Q  + 32*DIM*HW)
#define OUT_CNT  (OUT_IDX + NTOK)
#define OUT_W    (OUT_CNT + K_CODES)
#define OUT_CB   (OUT_W   + K_CODES*DIM)

#define WINDOW 3.0e-4f
#define NTILE  (K_CODES / 128)   // 64

// ---------------- device scratch ----------------
__device__ __align__(128) __half g_x16T[NTOK * DIM];     // half(x), [token][d]
__device__ __align__(128) __half g_cb16[K_CODES * DIM];  // half(cb * 2^13), [code][d]
__device__ __align__(128) __half g_dhh16[(size_t)NTOK * K_CODES]; // fp16 d_scan
__device__ __align__(128) float  g_tmin[NTILE * NTOK];   // [tile][token] tile minima
__device__ float  g_cbnorm[K_CODES];
__device__ float  g_znorm[NTOK];
__device__ double g_zpart[8][NTOK];
__device__ float  g_counts[K_CODES];
__device__ float  g_dw[K_CODES * DIM];
__device__ double g_loss;
__device__ int    g_idx[NTOK];

__device__ __forceinline__ uint32_t smem_u32(const void* p) {
    uint32_t a;
    asm("{ .reg .u64 t; cvta.to.shared.u64 t, %1; cvt.u32.u64 %0, t; }" : "=r"(a) : "l"(p));
    return a;
}
#define CP16(dst, src) \
    asm volatile("cp.async.ca.shared.global [%0], [%1], 16;" :: "r"(dst), "l"(src))
#define CP_COMMIT() asm volatile("cp.async.commit_group;" ::: "memory")
#define CP_WAIT0()  asm volatile("cp.async.wait_group 0;" ::: "memory")

#define MMA_F16(c, a, b) \
    asm volatile("mma.sync.aligned.m16n8k16.row.col.f32.f16.f16.f32 " \
        "{%0,%1,%2,%3}, {%4,%5,%6,%7}, {%8,%9}, {%0,%1,%2,%3};" \
        : "+f"((c)[0]), "+f"((c)[1]), "+f"((c)[2]), "+f"((c)[3]) \
        : "r"((a)[0]), "r"((a)[1]), "r"((a)[2]), "r"((a)[3]), "r"((b)[0]), "r"((b)[1]))

// ---------------- init ----------------
__global__ void init_kernel() {
    int i = blockIdx.x * blockDim.x + threadIdx.x;
    if (i < K_CODES * DIM) g_dw[i] = 0.0f;
    if (i < K_CODES)       g_counts[i] = 0.0f;
    if (i == 0)            g_loss = 0.0;
}

// ---------------- x -> half [token][d]  +  znorm partials (fused) ----------------
__global__ void decomp_x16T(const float* __restrict__ x) {
    __shared__ float tile[32][33];
    int tx = threadIdx.x, ty = threadIdx.y;
    int hw0 = blockIdx.x * 32, d0 = blockIdx.y * 32, b = blockIdx.z;
    tile[ty][tx] = x[(size_t)b * DIM * HW + (size_t)(d0 + ty) * HW + hw0 + tx];
    __syncthreads();
    float v = tile[tx][ty];                       // token = b*1024+hw0+ty, d = d0+tx
    int token = b * 1024 + hw0 + ty;
    g_x16T[(size_t)token * DIM + d0 + tx] = __float2half_rn(v);
    double s = (double)v * (double)v;
    #pragma unroll
    for (int o = 16; o; o >>= 1) s += __shfl_down_sync(0xFFFFFFFFu, s, o);
    if (tx == 0) g_zpart[d0 >> 5][token] = s;
}
__global__ void znorm_comb() {
    int token = blockIdx.x * blockDim.x + threadIdx.x;
    double a0 = (g_zpart[0][token] + g_zpart[1][token])
              + (g_zpart[2][token] + g_zpart[3][token]);
    double a1 = (g_zpart[4][token] + g_zpart[5][token])
              + (g_zpart[6][token] + g_zpart[7][token]);
    g_znorm[token] = (float)(a0 + a1);
}

// ---------------- cb -> half(cb*2^13) + cbnorm (fused; warp per code) ----------
__global__ void decomp_cb16(const float* __restrict__ cb) {
    int gw = (blockIdx.x * blockDim.x + threadIdx.x) >> 5;  // code
    int lane = threadIdx.x & 31;
    const float* r = cb + (size_t)gw * DIM + lane * 8;
    float4 v0 = *(const float4*)r;
    float4 v1 = *(const float4*)(r + 4);
    __half2 h[4];
    h[0] = __floats2half2_rn(v0.x * 8192.0f, v0.y * 8192.0f);
    h[1] = __floats2half2_rn(v0.z * 8192.0f, v0.w * 8192.0f);
    h[2] = __floats2half2_rn(v1.x * 8192.0f, v1.y * 8192.0f);
    h[3] = __floats2half2_rn(v1.z * 8192.0f, v1.w * 8192.0f);
    *(uint4*)(g_cb16 + (size_t)gw * DIM + lane * 8) = *(uint4*)h;
    double s = 0.0;
    const float vv[8] = {v0.x, v0.y, v0.z, v0.w, v1.x, v1.y, v1.z, v1.w};
    #pragma unroll
    for (int i = 0; i < 8; i++) s = fma((double)vv[i], (double)vv[i], s);
    #pragma unroll
    for (int o = 16; o; o >>= 1) s += __shfl_down_sync(0xFFFFFFFFu, s, o);
    if (lane == 0) g_cbnorm[gw] = (float)s;
}

// ---------------- fp16 screening GEMM + per-tile minima (R14-proven) ------------
#define AP      40
#define TILE_H  (128 * AP)
#define STAGE_H (2 * TILE_H)
#define NKSTEP  8
#define EPI_P   136
#define SMEM_B  (2 * STAGE_H * 2)     // 40960 B

__global__ void __launch_bounds__(256, 2)
screen_gemm16(void) {
    extern __shared__ __half smh[];
    const uint32_t smb = smem_u32(smh);

    const int tid  = threadIdx.x;
    const int lane = tid & 31;
    const int wid  = tid >> 5;
    const int g    = lane >> 2;
    const int q    = lane & 3;

    const int tb  = blockIdx.y;
    const int ct  = blockIdx.x;
    const int nt0 = ct * 128;

    const int mbase = (wid & 3) * 32;
    const int nbase = (wid >> 2) * 64;

    float acc[2][8][4];
    #pragma unroll
    for (int mf = 0; mf < 2; mf++)
        #pragma unroll
        for (int nf = 0; nf < 8; nf++)
            #pragma unroll
            for (int c = 0; c < 4; c++) acc[mf][nf][c] = 0.0f;

    auto issue = [&](int s, int k0) {
        const __half* ap = g_x16T + (size_t)(tb * 128) * DIM + k0;
        const __half* bp = g_cb16 + (size_t)nt0 * DIM + k0;
        #pragma unroll
        for (int i = 0; i < 2; i++) {
            int idx = i * 256 + tid;
            int row = idx >> 2;
            int seg = idx & 3;
            CP16(smb + 2u * (s * STAGE_H + row * AP + seg * 8),
                 ap + (size_t)row * DIM + seg * 8);
            CP16(smb + 2u * (s * STAGE_H + TILE_H + row * AP + seg * 8),
                 bp + (size_t)row * DIM + seg * 8);
        }
        CP_COMMIT();
    };

    issue(0, 0);

    #pragma unroll 1
    for (int ks = 0; ks < NKSTEP; ks++) {
        CP_WAIT0();
        __syncthreads();
        if (ks < NKSTEP - 1) issue((ks + 1) & 1, (ks + 1) * 32);

        const uint32_t* A32 = (const uint32_t*)(smh + (ks & 1) * STAGE_H);
        const uint32_t* B32 = A32 + TILE_H / 2;

        #pragma unroll
        for (int kl2 = 0; kl2 < 2; kl2++) {
            const int klh = kl2 * 8;
            uint32_t af[2][4], bf[8][2];
            #pragma unroll
            for (int mf = 0; mf < 2; mf++) {
                int m = mbase + mf * 16 + g;
                af[mf][0] = A32[m * (AP / 2) + klh + q];
                af[mf][1] = A32[(m + 8) * (AP / 2) + klh + q];
                af[mf][2] = A32[m * (AP / 2) + klh + 4 + q];
                af[mf][3] = A32[(m + 8) * (AP / 2) + klh + 4 + q];
            }
            #pragma unroll
            for (int nf = 0; nf < 8; nf++) {
                int n = nbase + nf * 8 + g;
                bf[nf][0] = B32[n * (AP / 2) + klh + q];
                bf[nf][1] = B32[n * (AP / 2) + klh + 4 + q];
            }
            #pragma unroll
            for (int mf = 0; mf < 2; mf++)
                #pragma unroll
                for (int nf = 0; nf < 8; nf++)
                    MMA_F16(acc[mf][nf], af[mf], bf[nf]);
        }
    }

    // epilogue: d_scan = fmaf(-2^-12, dot_scaled, cn); stage fp16 in smem.
    __syncthreads();
    #pragma unroll
    for (int mf = 0; mf < 2; mf++)
        #pragma unroll
        for (int h = 0; h < 2; h++) {
            int m = mbase + mf * 16 + g + h * 8;
            #pragma unroll
            for (int nf = 0; nf < 8; nf++) {
                int n = nbase + nf * 8 + q * 2;
                float d0 = fmaf(-0.000244140625f, acc[mf][nf][h * 2 + 0],
                                __ldg(&g_cbnorm[nt0 + n]));
                float d1 = fmaf(-0.000244140625f, acc[mf][nf][h * 2 + 1],
                                __ldg(&g_cbnorm[nt0 + n + 1]));
                *(__half2*)&smh[m * EPI_P + n] = __floats2half2_rn(d0, d1);
            }
        }
    __syncthreads();
    if (tid < 128) {
        const __half2* rp = (const __half2*)&smh[tid * EPI_P];
        float mn = CUDART_INF_F;
        #pragma unroll
        for (int i = 0; i < 64; i++) {
            float2 f = __half22float2(rp[i]);
            mn = fminf(mn, fminf(f.x, f.y));
        }
        g_tmin[(size_t)ct * NTOK + tb * 128 + tid] = mn;
    }
    __half* drow = g_dhh16 + (size_t)(tb * 128) * K_CODES + nt0;
    #pragma unroll
    for (int i = 0; i < 8; i++) {
        int idx = i * 256 + tid;
        int row = idx >> 4;
        int ch  = idx & 15;
        uint4 v = *(const uint4*)&smh[row * EPI_P + ch * 8];
        *(uint4*)(drow + (size_t)row * K_CODES + ch * 8) = v;
    }
}

// ---------------- scan (tile-min pruned) + rescore: one block per token ----------
#define MAXCAND 512
__global__ void __launch_bounds__(256, 4)
scan_rescore(const float* __restrict__ x, const float* __restrict__ cb,
             float* __restrict__ out) {
    __shared__ float stmin[NTILE];
    __shared__ int   sqtiles[NTILE];
    __shared__ int   sqcnt;
    __shared__ float sthr;
    __shared__ int   scnt;
    __shared__ int   scand[MAXCAND];
    __shared__ unsigned long long sbest;

    const int t = blockIdx.x;
    const int tid = threadIdx.x, lane = tid & 31, wid = tid >> 5;

    if (tid < NTILE) stmin[tid] = g_tmin[(size_t)tid * NTOK + t];
    if (tid == 0) { sqcnt = 0; scnt = 0; sbest = 0xFFFFFFFFFFFFFFFFull; }
    __syncthreads();

    if (wid == 0) {
        float mm = fminf(stmin[lane], stmin[lane + 32]);
        #pragma unroll
        for (int o = 16; o; o >>= 1) mm = fminf(mm, __shfl_down_sync(0xFFFFFFFFu, mm, o));
        if (lane == 0) sthr = mm + WINDOW;
    }
    __syncthreads();
    const float thr = sthr;

    if (tid < NTILE && stmin[tid] <= thr) {
        int p = atomicAdd(&sqcnt, 1);
        sqtiles[p] = tid;
    }
    __syncthreads();

    for (int qi = wid; qi < sqcnt; qi += 8) {
        int ct = sqtiles[qi];
        const __half2* dp = (const __half2*)(g_dhh16 + (size_t)t * K_CODES + ct * 128);
        #pragma unroll
        for (int i = 0; i < 2; i++) {
            float2 f = __half22float2(dp[lane + i * 32]);
            int base = ct * 128 + (lane + i * 32) * 2;
            if (f.x <= thr) {
                int p = atomicAdd(&scnt, 1);
                if (p < MAXCAND) scand[p] = base;
            }
            if (f.y <= thr) {
                int p = atomicAdd(&scnt, 1);
                if (p < MAXCAND) scand[p] = base + 1;
            }
        }
    }
    __syncthreads();
    int ncand = min(scnt, MAXCAND);

    const int b = t >> 10, hw = t & 1023;
    const float* xbase = x + (size_t)b * DIM * HW + hw;
    const float zn = g_znorm[t];

    for (int j = wid; j < ncand; j += 8) {
        int c = scand[j];
        const float* crow = cb + (size_t)c * DIM;
        double s = 0.0;
        #pragma unroll
        for (int i = 0; i < 8; i++) {
            int d = lane + i * 32;
            double xv = (double)__ldg(xbase + (size_t)d * HW);
            double cv = (double)__ldg(crow + d);
            s = fma(xv, cv, s);
        }
        #pragma unroll
        for (int o = 16; o; o >>= 1) s += __shfl_down_sync(0xFFFFFFFFu, s, o);
        if (lane == 0) {
            float dotf = (float)s;
            float t1 = __fadd_rn(zn, __ldg(&g_cbnorm[c]));
            float d  = __fsub_rn(t1, __fmul_rn(2.0f, dotf));
            unsigned int e = __float_as_uint(d);
            e = (e & 0x80000000u) ? ~e : (e | 0x80000000u);
            atomicMin(&sbest, ((unsigned long long)e << 32) | (unsigned int)c);
        }
    }
    __syncthreads();
    if (tid == 0) {
        int id = (int)(sbest & 0xFFFFFFFFull);
        g_idx[t] = id;
        out[OUT_IDX + t] = (float)id;
        atomicAdd(&g_counts[id], 1.0f);
    }
}

// ---------------- quantized output + loss + dw (fused, coalesced) ----------------
__global__ void quant_loss_dw(const float* __restrict__ x,
                              const float* __restrict__ cb,
                              float* __restrict__ out) {
    int c = blockIdx.x, b = blockIdx.y;
    int tid = threadIdx.x, lane = tid & 31;
    float ls = 0.0f;
    #pragma unroll
    for (int it = 0; it < 4; it++) {
        int hw = it * 256 + tid;
        int n  = (b << 10) + hw;
        int id = g_idx[n];
        float qv = __ldg(cb + (size_t)id * DIM + c);
        size_t off = (size_t)b * DIM * HW + (size_t)c * HW + hw;
        float xv = x[off];
        out[OUT_Q + off] = __fadd_rn(xv, __fsub_rn(qv, xv));
        float d = __fsub_rn(qv, xv);
        ls = fmaf(d, d, ls);
        atomicAdd(&g_dw[(size_t)id * DIM + c], xv);
    }
    double ds = (double)ls;
    #pragma unroll
    for (int o = 16; o; o >>= 1) ds += __shfl_down_sync(0xFFFFFFFFu, ds, o);
    if (lane == 0) atomicAdd(&g_loss, ds);
}

// ---------------- EMA finalize ----------------
__global__ void final_kernel(const float* __restrict__ ema_count,
                             const float* __restrict__ ema_weight,
                             float* __restrict__ out) {
    int k = blockIdx.x;
    int c = threadIdx.x;
    float nc = ema_count[k] * 0.95f + 0.05f * g_counts[k];
    const float denom = (float)(32768.0 + 8192.0 * 1e-5);
    nc = (nc + 1e-5f) / denom * 32768.0f;
    float w = ema_weight[(size_t)k * DIM + c] * 0.95f + 0.05f * g_dw[(size_t)k * DIM + c];
    out[OUT_W  + (size_t)k * DIM + c] = w;
    out[OUT_CB + (size_t)k * DIM + c] = w / nc;
    if (c == 0) out[OUT_CNT + k] = nc;
    if (k == 0 && c == 0) {
        double mean = g_loss / (double)((size_t)NTOK * DIM);
        out[OUT_LOSS] = 0.25f * (float)mean;
    }
}

extern "C" void kernel_launch(void* const* d_in, const int* in_sizes, int n_in,
                              void* d_out, int out_size) {
    const float* x          = (const float*)d_in[0];
    const float* cb         = (const float*)d_in[1];
    const float* ema_count  = (const float*)d_in[2];
    const float* ema_weight = (const float*)d_in[3];
    float* out = (float*)d_out;

    static int smem_set = 0;
    if (!smem_set) {
        cudaFuncSetAttribute(screen_gemm16,
                             cudaFuncAttributeMaxDynamicSharedMemorySize, SMEM_B);
        smem_set = 1;
    }

    init_kernel<<<(K_CODES * DIM + 255) / 256, 256>>>();
    decomp_x16T<<<dim3(HW / 32, DIM / 32, 32), dim3(32, 32)>>>(x);
    znorm_comb<<<NTOK / 256, 256>>>();
    decomp_cb16<<<K_CODES * 32 / 256, 256>>>(cb);
    screen_gemm16<<<dim3(K_CODES / 128, NTOK / 128), 256, SMEM_B>>>();
    scan_rescore<<<NTOK, 256>>>(x, cb, out);
    quant_loss_dw<<<dim3(DIM, 32), 256>>>(x, cb, out);
    final_kernel<<<K_CODES, DIM>>>(ema_count, ema_weight, out);
}